// round 7
// baseline (speedup 1.0000x reference)
#include <cuda_runtime.h>
#include <cstdint>

// ---------------------------------------------------------------------------
// Fused recurrent decoder: B=32768, T=30, D=384, FF=1024, HID=64.
// One block = 64 rows, all 30 steps. TF32 mma.sync.
// Ring-3 cp.async weight staging with wait_group 1 (prefetch distance 2).
// ---------------------------------------------------------------------------

#define B_TOTAL   32768
#define T_STEPS   30
#define D_DIM     384
#define FF_DIM    1024
#define NTH       256

#define LDA   388   // xs stride   (mod 32 == 4 -> conflict-free frags)
#define LDY   132   // ych stride  (mod 32 == 4)
#define LDSP  28    // producer stage stride [128 x 24] (28 mod 32 spread OK)
#define LDSC  12    // consumer stage stride [384 x 8]  (12 mod 32 spread OK)
#define LDSD  52    // decoder stage stride  [64 x 48]

// shared memory float offsets
#define XS     0                 // 24832
#define YCH    24832             // 8448
#define RG0    33280             // 4608
#define RG1    37888             // 4608
#define RG2    42496             // 4608
#define WP_    47104             // 1152
#define WS_    48256             // 1152
#define BP_    49408             // 384
#define BS_    49792             // 384
#define BV_    50176             // 384
#define BO_    50560             // 384
#define B1_    50944             // 1024
#define B2_    51968             // 384
#define G1_    52352             // 384
#define BE1_   52736             // 384
#define G2_    53120             // 384
#define BE2_   53504             // 384
#define BD1_   53888             // 64
#define WD2_   53952             // 192
#define BD2_   54144             // 4
#define GATE_  54148             // 64
#define STATE_ 54212             // 192
#define PLAN_  54404             // 192
#define RED_   54596             // 512
#define SMEM_FLOATS 55108
#define SMEM_BYTES  (SMEM_FLOATS * 4)   // 220432 B

__device__ __forceinline__ uint32_t f2tf(float x) {
    uint32_t u;
    asm("cvt.rna.tf32.f32 %0, %1;" : "=r"(u) : "f"(x));
    return u;
}

__device__ __forceinline__ void mma8(float* c, uint32_t a0, uint32_t a1,
                                     uint32_t a2, uint32_t a3,
                                     uint32_t b0, uint32_t b1) {
    asm volatile(
        "mma.sync.aligned.m16n8k8.row.col.f32.tf32.tf32.f32 "
        "{%0,%1,%2,%3}, {%4,%5,%6,%7}, {%8,%9}, {%0,%1,%2,%3};"
        : "+f"(c[0]), "+f"(c[1]), "+f"(c[2]), "+f"(c[3])
        : "r"(a0), "r"(a1), "r"(a2), "r"(a3), "r"(b0), "r"(b1));
}

__device__ __forceinline__ void cp16(float* dst, const float* src) {
    uint32_t d = (uint32_t)__cvta_generic_to_shared(dst);
    asm volatile("cp.async.cg.shared.global [%0], [%1], 16;" :: "r"(d), "l"(src));
}
__device__ __forceinline__ void cp_commit() {
    asm volatile("cp.async.commit_group;" ::: "memory");
}
__device__ __forceinline__ void cp_wait0() {
    asm volatile("cp.async.wait_group 0;" ::: "memory");
}
__device__ __forceinline__ void cp_wait1() {
    asm volatile("cp.async.wait_group 1;" ::: "memory");
}

// stage prefetchers: 768 cp16 chunks, 3 per thread
__device__ __forceinline__ void pf_prod(float* buf, const float* Wg, int st, int tid) {
    const float* src = Wg + st * 24;
#pragma unroll
    for (int i = 0; i < 3; i++) {
        int q = tid + i * NTH;            // 0..767
        int n = q / 6, kq = q - n * 6;    // 128 rows x 6 chunks
        cp16(buf + n * LDSP + kq * 4, src + (size_t)n * D_DIM + kq * 4);
    }
    cp_commit();
}
__device__ __forceinline__ void pf_cons(float* buf, const float* Wbase, int ldw, int st, int tid) {
    const float* src = Wbase + st * 8;
#pragma unroll
    for (int i = 0; i < 3; i++) {
        int q = tid + i * NTH;            // 0..767
        int n = q >> 1, kq = q & 1;       // 384 rows x 2 chunks
        cp16(buf + n * LDSC + kq * 4, src + (size_t)n * ldw + kq * 4);
    }
    cp_commit();
}

// ---------------------------------------------------------------------------
// Producer (128-wide): ych[64 x 128] = ACT( xs[64x384] @ Wg[128 x 384]^T + b )
// Warp: pm = w>>2 (2 m16-tiles at pm*32+mt*16), pn = w&3 (4 n8-tiles j*32+pn*8).
// 16 k-stages of 24, ring-3, prefetch distance 2.
// ---------------------------------------------------------------------------
template<int ACT>
__device__ __forceinline__ void producer128(
    const float* __restrict__ Wg, const float* __restrict__ bias,
    float* __restrict__ sm, int pm, int pn, int lane, int tid)
{
    float* xs  = sm + XS;
    float* ych = sm + YCH;

    float pacc[32];
#pragma unroll
    for (int i = 0; i < 32; i++) pacc[i] = 0.f;

    __syncthreads();                       // ring + ych/xs safe from prev phase
    float* b0 = sm + RG0;
    float* b1 = sm + RG1;
    float* b2 = sm + RG2;
    pf_prod(b0, Wg, 0, tid);
    pf_prod(b1, Wg, 1, tid);

#pragma unroll 1
    for (int st = 0; st < 16; ++st) {
        if (st < 15) cp_wait1(); else cp_wait0();
        __syncthreads();
        if (st < 14) pf_prod(b2, Wg, st + 2, tid);

#pragma unroll
        for (int k8 = 0; k8 < 3; k8++) {
            uint32_t a[2][4];
#pragma unroll
            for (int mt = 0; mt < 2; mt++) {
                const float* ap = xs + (pm * 32 + mt * 16 + (lane >> 2)) * LDA
                                     + st * 24 + k8 * 8 + (lane & 3);
                a[mt][0] = __float_as_uint(ap[0]);
                a[mt][1] = __float_as_uint(ap[8 * LDA]);
                a[mt][2] = __float_as_uint(ap[4]);
                a[mt][3] = __float_as_uint(ap[8 * LDA + 4]);
            }
#pragma unroll
            for (int j = 0; j < 4; j++) {
                const float* bp = b0 + (j * 32 + pn * 8 + (lane >> 2)) * LDSP
                                     + k8 * 8 + (lane & 3);
                uint32_t w0 = __float_as_uint(bp[0]);
                uint32_t w1 = __float_as_uint(bp[4]);
#pragma unroll
                for (int mt = 0; mt < 2; mt++)
                    mma8(pacc + (mt * 4 + j) * 4,
                         a[mt][0], a[mt][1], a[mt][2], a[mt][3], w0, w1);
            }
        }
        float* tmp = b0; b0 = b1; b1 = b2; b2 = tmp;
    }

    // epilogue: bias + activation + RNA tf32 round, write ych
#pragma unroll
    for (int mt = 0; mt < 2; mt++) {
        int r0 = pm * 32 + mt * 16 + (lane >> 2);
#pragma unroll
        for (int j = 0; j < 4; j++) {
            int n0 = j * 32 + pn * 8 + ((lane & 3) << 1);
            float bb0 = bias[n0], bb1 = bias[n0 + 1];
            float v[4];
            v[0] = pacc[(mt * 4 + j) * 4 + 0] + bb0;
            v[1] = pacc[(mt * 4 + j) * 4 + 1] + bb1;
            v[2] = pacc[(mt * 4 + j) * 4 + 2] + bb0;
            v[3] = pacc[(mt * 4 + j) * 4 + 3] + bb1;
#pragma unroll
            for (int cc = 0; cc < 4; cc++) {
                float x = v[cc];
                if (ACT == 1) x = fmaxf(x, 0.f);
                v[cc] = __uint_as_float(f2tf(x));
            }
            ych[r0 * LDY + n0]           = v[0];
            ych[r0 * LDY + n0 + 1]       = v[1];
            ych[(r0 + 8) * LDY + n0]     = v[2];
            ych[(r0 + 8) * LDY + n0 + 1] = v[3];
        }
    }
}

// ---------------------------------------------------------------------------
// Consumer: acc[64 x 384] += ych[64 x 128] @ Wc[384 n x 128 k]^T
// Wbase = Wc + cblk*128. 16 k-stages of 8, ring-3, prefetch distance 2.
// Warp: mg = w>>2 (2 m-tiles mg*32+mt*16), ng = w&3 (12 n-tiles j*32+ng*8).
// ---------------------------------------------------------------------------
__device__ __forceinline__ void consumer128(
    const float* __restrict__ Wc, int ldw, int cblk,
    float* __restrict__ sm, float (&acc)[96],
    int mg, int ng, int lane, int tid)
{
    float* ych = sm + YCH;
    const float* Wbase = Wc + cblk * 128;

    __syncthreads();                       // ring + ych safe from producer
    float* b0 = sm + RG0;
    float* b1 = sm + RG1;
    float* b2 = sm + RG2;
    pf_cons(b0, Wbase, ldw, 0, tid);
    pf_cons(b1, Wbase, ldw, 1, tid);

#pragma unroll 1
    for (int st = 0; st < 16; ++st) {
        if (st < 15) cp_wait1(); else cp_wait0();
        __syncthreads();
        if (st < 14) pf_cons(b2, Wbase, ldw, st + 2, tid);

        uint32_t a[2][4];
#pragma unroll
        for (int mt = 0; mt < 2; mt++) {
            const float* ap = ych + ((mg * 2 + mt) * 16 + (lane >> 2)) * LDY
                                  + st * 8 + (lane & 3);
            a[mt][0] = __float_as_uint(ap[0]);
            a[mt][1] = __float_as_uint(ap[8 * LDY]);
            a[mt][2] = __float_as_uint(ap[4]);
            a[mt][3] = __float_as_uint(ap[8 * LDY + 4]);
        }
#pragma unroll
        for (int j = 0; j < 12; j++) {
            const float* bp = b0 + (j * 32 + ng * 8 + (lane >> 2)) * LDSC + (lane & 3);
            uint32_t w0 = __float_as_uint(bp[0]);
            uint32_t w1 = __float_as_uint(bp[4]);
            mma8(acc + (j * 2 + 0) * 4, a[0][0], a[0][1], a[0][2], a[0][3], w0, w1);
            mma8(acc + (j * 2 + 1) * 4, a[1][0], a[1][1], a[1][2], a[1][3], w0, w1);
        }
        float* tmp = b0; b0 = b1; b1 = b2; b2 = tmp;
    }
}

// ---------------------------------------------------------------------------
// LN epilogue: xs <- LN(xs + acc) * g + be
// ---------------------------------------------------------------------------
__device__ __forceinline__ void ln_epilogue(
    float* __restrict__ sm, float (&acc)[96],
    const float* __restrict__ g, const float* __restrict__ be,
    int mg, int ng, int lane)
{
    float*  xs  = sm + XS;
    float2* red = reinterpret_cast<float2*>(sm + RED_);

    float s4[4], q4[4];
#pragma unroll
    for (int i = 0; i < 4; i++) { s4[i] = 0.f; q4[i] = 0.f; }

#pragma unroll
    for (int j = 0; j < 12; j++)
#pragma unroll
        for (int mt = 0; mt < 2; mt++)
#pragma unroll
            for (int cc = 0; cc < 4; cc++) {
                int r = mg * 32 + mt * 16 + (lane >> 2) + ((cc >> 1) << 3);
                int n = j * 32 + ng * 8 + ((lane & 3) << 1) + (cc & 1);
                float v = xs[r * LDA + n] + acc[(j * 2 + mt) * 4 + cc];
                xs[r * LDA + n] = v;
                int ri = mt * 2 + (cc >> 1);
                s4[ri] += v;
                q4[ri] += v * v;
            }
#pragma unroll
    for (int d = 1; d < 4; d <<= 1)
#pragma unroll
        for (int i = 0; i < 4; i++) {
            s4[i] += __shfl_xor_sync(0xffffffffu, s4[i], d);
            q4[i] += __shfl_xor_sync(0xffffffffu, q4[i], d);
        }
    if ((lane & 3) == 0) {
#pragma unroll
        for (int i = 0; i < 4; i++) {
            int r = mg * 32 + (i >> 1) * 16 + (lane >> 2) + ((i & 1) << 3);
            red[r * 4 + ng] = make_float2(s4[i], q4[i]);
        }
    }
    __syncthreads();

#pragma unroll
    for (int i = 0; i < 4; i++) {
        int mt = i >> 1, h = i & 1;
        int r = mg * 32 + mt * 16 + (lane >> 2) + h * 8;
        float S = 0.f, Q = 0.f;
#pragma unroll
        for (int w = 0; w < 4; w++) { float2 tv = red[r * 4 + w]; S += tv.x; Q += tv.y; }
        float m   = S * (1.f / 384.f);
        float var = Q * (1.f / 384.f) - m * m;
        float rs  = rsqrtf(var + 1e-5f);
#pragma unroll
        for (int j = 0; j < 12; j++)
#pragma unroll
            for (int cc = 0; cc < 2; cc++) {
                int n = j * 32 + ng * 8 + ((lane & 3) << 1) + cc;
                float v = xs[r * LDA + n];
                xs[r * LDA + n] = (v - m) * rs * g[n] + be[n];
            }
    }
}

// ---------------------------------------------------------------------------
// Decoder producer (64-wide, RNA staging for state-path accuracy):
// ych[64 x 64] = elu( xs @ Wd1[64 x 384]^T + bd1 ), fp32 output.
// ---------------------------------------------------------------------------
__device__ __forceinline__ void producer_dec(
    const float* __restrict__ Wd1, const float* __restrict__ bias,
    float* __restrict__ sm, int wm, int wn, int lane, int tid)
{
    float* xs  = sm + XS;
    float* ych = sm + YCH;
    float* bt  = sm + RG0;

    float pacc[16];
#pragma unroll
    for (int i = 0; i < 16; i++) pacc[i] = 0.f;

#pragma unroll 1
    for (int st = 0; st < 8; st++) {
        __syncthreads();
#pragma unroll
        for (int i = 0; i < 3; i++) {
            int q = tid + i * NTH;           // 0..767; 64 rows x 12 chunks
            int n = q / 12, kq = q - n * 12;
            float4 v = *reinterpret_cast<const float4*>(Wd1 + (size_t)n * D_DIM + st * 48 + kq * 4);
            float4 w;
            w.x = __uint_as_float(f2tf(v.x));
            w.y = __uint_as_float(f2tf(v.y));
            w.z = __uint_as_float(f2tf(v.z));
            w.w = __uint_as_float(f2tf(v.w));
            *reinterpret_cast<float4*>(bt + n * LDSD + kq * 4) = w;
        }
        __syncthreads();
#pragma unroll
        for (int k8 = 0; k8 < 6; k8++) {
            const float* ap = xs + (wm * 16 + (lane >> 2)) * LDA + st * 48 + k8 * 8 + (lane & 3);
            uint32_t a0 = f2tf(ap[0]);
            uint32_t a1 = f2tf(ap[8 * LDA]);
            uint32_t a2 = f2tf(ap[4]);
            uint32_t a3 = f2tf(ap[8 * LDA + 4]);
#pragma unroll
            for (int tl = 0; tl < 4; tl++) {
                const float* bp = bt + (wn * 32 + tl * 8 + (lane >> 2)) * LDSD + k8 * 8 + (lane & 3);
                mma8(pacc + tl * 4, a0, a1, a2, a3,
                     __float_as_uint(bp[0]), __float_as_uint(bp[4]));
            }
        }
    }

    int r0 = wm * 16 + (lane >> 2);
#pragma unroll
    for (int tl = 0; tl < 4; tl++) {
        int n0 = wn * 32 + tl * 8 + ((lane & 3) << 1);
        float bb0 = bias[n0], bb1 = bias[n0 + 1];
        float v[4];
        v[0] = pacc[tl * 4 + 0] + bb0;
        v[1] = pacc[tl * 4 + 1] + bb1;
        v[2] = pacc[tl * 4 + 2] + bb0;
        v[3] = pacc[tl * 4 + 3] + bb1;
#pragma unroll
        for (int cc = 0; cc < 4; cc++) { float x = v[cc]; v[cc] = (x > 0.f) ? x : expm1f(x); }
        ych[r0 * LDY + n0]           = v[0];
        ych[r0 * LDY + n0 + 1]       = v[1];
        ych[(r0 + 8) * LDY + n0]     = v[2];
        ych[(r0 + 8) * LDY + n0 + 1] = v[3];
    }
}

__device__ __forceinline__ void cpy(float* __restrict__ dst,
                                    const float* __restrict__ src,
                                    int n, int tid)
{
    for (int i = tid; i < n; i += NTH) dst[i] = src[i];
}

// ---------------------------------------------------------------------------
// Main kernel
// ---------------------------------------------------------------------------
extern "C" __global__ void __launch_bounds__(NTH, 1)
decoder_fused_kernel(
    const float* __restrict__ ih,     const float* __restrict__ plan,
    const float* __restrict__ gate,   const float* __restrict__ init_state,
    const float* __restrict__ Wp,     const float* __restrict__ bp,
    const float* __restrict__ Ws,     const float* __restrict__ bs,
    const float* __restrict__ Wqkv,   const float* __restrict__ bqkv,
    const float* __restrict__ Wo,     const float* __restrict__ bo,
    const float* __restrict__ g1,     const float* __restrict__ be1,
    const float* __restrict__ g2,     const float* __restrict__ be2,
    const float* __restrict__ W1,     const float* __restrict__ b1,
    const float* __restrict__ W2,     const float* __restrict__ b2,
    const float* __restrict__ Wd1,    const float* __restrict__ bd1,
    const float* __restrict__ Wd2,    const float* __restrict__ bd2,
    float* __restrict__ out)
{
    extern __shared__ float sm[];
    const int tid  = threadIdx.x;
    const int lane = tid & 31;
    const int w    = tid >> 5;
    const int pm = w >> 2, pn = w & 3;   // producer128 layout
    const int mg = w >> 2, ng = w & 3;   // consumer layout
    const int wm = w >> 1, wn = w & 1;   // decoder producer layout
    const int row0 = blockIdx.x * 64;

    const float* Wv = Wqkv + 2 * D_DIM * D_DIM;
    const float* bv = bqkv + 2 * D_DIM;

    // one-time parameter staging
    cpy(sm + WP_,  Wp,  1152, tid);
    cpy(sm + WS_,  Ws,  1152, tid);
    cpy(sm + BP_,  bp,   384, tid);
    cpy(sm + BS_,  bs,   384, tid);
    cpy(sm + BV_,  bv,   384, tid);
    cpy(sm + BO_,  bo,   384, tid);
    cpy(sm + B1_,  b1,  1024, tid);
    cpy(sm + B2_,  b2,   384, tid);
    cpy(sm + G1_,  g1,   384, tid);
    cpy(sm + BE1_, be1,  384, tid);
    cpy(sm + G2_,  g2,   384, tid);
    cpy(sm + BE2_, be2,  384, tid);
    cpy(sm + BD1_, bd1,   64, tid);
    cpy(sm + WD2_, Wd2,  192, tid);
    cpy(sm + BD2_, bd2,    3, tid);
    if (tid < 64)  sm[GATE_  + tid] = gate[row0 + tid];
    if (tid < 192) sm[STATE_ + tid] = init_state[(size_t)row0 * 3 + tid];

    const float* ihrow = ih + (size_t)row0 * D_DIM;

    for (int t = 0; t < T_STEPS; t++) {
        __syncthreads();

        if (tid < 192) {
            int r = tid / 3, j = tid - r * 3;
            sm[PLAN_ + tid] = plan[((size_t)(row0 + r) * T_STEPS + t) * 3 + j];
        }
        __syncthreads();

        // x = sf + pf*gate + init_hidden
#pragma unroll 4
        for (int i = 0; i < 96; i++) {
            int idx = tid + i * NTH;
            int r = idx / D_DIM;
            int c = idx - r * D_DIM;
            float p0 = sm[PLAN_ + r * 3], p1 = sm[PLAN_ + r * 3 + 1], p2 = sm[PLAN_ + r * 3 + 2];
            float s0 = sm[STATE_ + r * 3], s1 = sm[STATE_ + r * 3 + 1], s2 = sm[STATE_ + r * 3 + 2];
            float pf = sm[BP_ + c] + p0 * sm[WP_ + c * 3] + p1 * sm[WP_ + c * 3 + 1] + p2 * sm[WP_ + c * 3 + 2];
            float sf = sm[BS_ + c] + s0 * sm[WS_ + c * 3] + s1 * sm[WS_ + c * 3 + 1] + s2 * sm[WS_ + c * 3 + 2];
            sm[XS + r * LDA + c] = sf + pf * sm[GATE_ + r] + ihrow[idx];
        }

        float acc[96];

        // ---- attention: attn = (x @ Wv^T + bv) @ Wo^T + bo
#pragma unroll
        for (int i = 0; i < 96; i++) acc[i] = 0.f;
        for (int c = 0; c < 3; c++) {
            producer128<0>(Wv + (size_t)c * 128 * D_DIM, sm + BV_ + c * 128, sm, pm, pn, lane, tid);
            consumer128(Wo, D_DIM, c, sm, acc, mg, ng, lane, tid);
        }
#pragma unroll
        for (int j = 0; j < 12; j++)
#pragma unroll
            for (int mt = 0; mt < 2; mt++)
#pragma unroll
                for (int cc = 0; cc < 4; cc++) {
                    int n = j * 32 + ng * 8 + ((lane & 3) << 1) + (cc & 1);
                    acc[(j * 2 + mt) * 4 + cc] += sm[BO_ + n];
                }
        ln_epilogue(sm, acc, sm + G1_, sm + BE1_, mg, ng, lane);

        // ---- FF: h = relu(x @ W1^T + b1) @ W2^T + b2
#pragma unroll
        for (int i = 0; i < 96; i++) acc[i] = 0.f;
        for (int c = 0; c < 8; c++) {
            producer128<1>(W1 + (size_t)c * 128 * D_DIM, sm + B1_ + c * 128, sm, pm, pn, lane, tid);
            consumer128(W2, FF_DIM, c, sm, acc, mg, ng, lane, tid);
        }
#pragma unroll
        for (int j = 0; j < 12; j++)
#pragma unroll
            for (int mt = 0; mt < 2; mt++)
#pragma unroll
                for (int cc = 0; cc < 4; cc++) {
                    int n = j * 32 + ng * 8 + ((lane & 3) << 1) + (cc & 1);
                    acc[(j * 2 + mt) * 4 + cc] += sm[B2_ + n];
                }
        ln_epilogue(sm, acc, sm + G2_, sm + BE2_, mg, ng, lane);

        // ---- decoder: hid = elu(x @ Wd1^T + bd1)  (fp32, RNA path)
        __syncthreads();   // ring slot 0 free (consumer st15 done before LN)
        producer_dec(Wd1, sm + BD1_, sm, wm, wn, lane, tid);
        __syncthreads();

        // upd = hid @ Wd2^T + bd2 ; nxt = state + upd ; emit + carry
        if (tid < 192) {
            int r = tid / 3, i = tid - r * 3;
            float u = sm[BD2_ + i];
            const float* y  = sm + YCH + r * LDY;
            const float* w2 = sm + WD2_ + i * 64;
#pragma unroll 16
            for (int j = 0; j < 64; j++) u += y[j] * w2[j];
            float nxt = sm[STATE_ + r * 3 + i] + u;
            out[((size_t)(row0 + r) * T_STEPS + t) * 3 + i] = nxt;
            sm[STATE_ + r * 3 + i] = nxt;
        }
    }
}

// ---------------------------------------------------------------------------
// launch
// ---------------------------------------------------------------------------
extern "C" void kernel_launch(void* const* d_in, const int* in_sizes, int n_in,
                              void* d_out, int out_size)
{
    (void)in_sizes; (void)n_in; (void)out_size;
    cudaFuncSetAttribute(decoder_fused_kernel,
                         cudaFuncAttributeMaxDynamicSharedMemorySize, SMEM_BYTES);
    decoder_fused_kernel<<<B_TOTAL / 64, NTH, SMEM_BYTES>>>(
        (const float*)d_in[0],  (const float*)d_in[1],  (const float*)d_in[2],
        (const float*)d_in[3],  (const float*)d_in[4],  (const float*)d_in[5],
        (const float*)d_in[6],  (const float*)d_in[7],  (const float*)d_in[8],
        (const float*)d_in[9],  (const float*)d_in[10], (const float*)d_in[11],
        (const float*)d_in[12], (const float*)d_in[13], (const float*)d_in[14],
        (const float*)d_in[15], (const float*)d_in[16], (const float*)d_in[17],
        (const float*)d_in[18], (const float*)d_in[19], (const float*)d_in[20],
        (const float*)d_in[21], (const float*)d_in[22], (const float*)d_in[23],
        (float*)d_out);
}

// round 9
// speedup vs baseline: 1.3456x; 1.3456x over previous
#include <cuda_runtime.h>
#include <cstdint>

// ---------------------------------------------------------------------------
// Fused recurrent decoder: B=32768, T=30, D=384, FF=1024, HID=64.
// One block = 64 rows, all 30 steps. TF32 mma.sync.
// Weight staging: 2-slot ring driven by mbarrier full/empty dataflow
// (cp.async.mbarrier.arrive), CTA-wide syncs only at true phase hazards.
// ---------------------------------------------------------------------------

#define B_TOTAL   32768
#define T_STEPS   30
#define D_DIM     384
#define FF_DIM    1024
#define NTH       256

#define LDA   388   // xs stride   (mod 32 == 4 -> conflict-free frags)
#define LDY   132   // ych stride  (mod 32 == 4)
#define LDSP  52    // producer stage stride [128 x 48]
#define LDSC  20    // consumer stage stride [384 x 16]
#define LDSD  100   // decoder stage stride  [64 x 96]

// shared memory float offsets
#define XS     0                 // 24832
#define YCH    24832             // 8448
#define RG0    33280             // 7680
#define RG1    40960             // 7680
#define WP_    48640             // 1152
#define WS_    49792             // 1152
#define BP_    50944             // 384
#define BS_    51328             // 384
#define BV_    51712             // 384
#define BO_    52096             // 384
#define B1_    52480             // 1024
#define B2_    53504             // 384
#define G1_    53888             // 384
#define BE1_   54272             // 384
#define G2_    54656             // 384
#define BE2_   55040             // 384
#define BD1_   55424             // 64
#define WD2_   55488             // 192
#define BD2_   55680             // 4
#define GATE_  55684             // 64
#define STATE_ 55748             // 192
#define PLAN_  55940             // 192
#define RED_   56132             // 512
#define MB_    56644             // 4 x u64 mbarriers: full0, full1, empty0, empty1
#define SMEM_FLOATS 56652
#define SMEM_BYTES  (SMEM_FLOATS * 4)   // 226608 B

__device__ __forceinline__ uint32_t f2tf(float x) {
    uint32_t u;
    asm("cvt.rna.tf32.f32 %0, %1;" : "=r"(u) : "f"(x));
    return u;
}

__device__ __forceinline__ void mma8(float* c, uint32_t a0, uint32_t a1,
                                     uint32_t a2, uint32_t a3,
                                     uint32_t b0, uint32_t b1) {
    asm volatile(
        "mma.sync.aligned.m16n8k8.row.col.f32.tf32.tf32.f32 "
        "{%0,%1,%2,%3}, {%4,%5,%6,%7}, {%8,%9}, {%0,%1,%2,%3};"
        : "+f"(c[0]), "+f"(c[1]), "+f"(c[2]), "+f"(c[3])
        : "r"(a0), "r"(a1), "r"(a2), "r"(a3), "r"(b0), "r"(b1));
}

__device__ __forceinline__ void cp16(float* dst, const float* src) {
    uint32_t d = (uint32_t)__cvta_generic_to_shared(dst);
    asm volatile("cp.async.cg.shared.global [%0], [%1], 16;" :: "r"(d), "l"(src));
}

// ---- mbarrier primitives -------------------------------------------------
__device__ __forceinline__ void mbar_init(uint32_t a, uint32_t cnt) {
    asm volatile("mbarrier.init.shared.b64 [%0], %1;" :: "r"(a), "r"(cnt) : "memory");
}
__device__ __forceinline__ void mbar_arrive(uint32_t a) {
    asm volatile("mbarrier.arrive.shared.b64 _, [%0];" :: "r"(a) : "memory");
}
__device__ __forceinline__ void cp_arrive(uint32_t a) {
    asm volatile("cp.async.mbarrier.arrive.noinc.shared.b64 [%0];" :: "r"(a) : "memory");
}
__device__ __forceinline__ void mbar_wait(uint32_t a, uint32_t parity) {
    asm volatile(
        "{\n\t"
        ".reg .pred P;\n\t"
        "WL_%=:\n\t"
        "mbarrier.try_wait.parity.acquire.cta.shared::cta.b64 P, [%0], %1, 0x989680;\n\t"
        "@P bra.uni WD_%=;\n\t"
        "bra.uni WL_%=;\n\t"
        "WD_%=:\n\t"
        "}"
        :: "r"(a), "r"(parity) : "memory");
}
__device__ __forceinline__ uint32_t full_a (uint32_t mb, int gs) { return mb      + (gs & 1) * 8; }
__device__ __forceinline__ uint32_t empty_a(uint32_t mb, int gs) { return mb + 16 + (gs & 1) * 8; }

// ---- ring loaders: acquire empty, issue cp.async, arrive full ------------
// producer tile: Wg[128 rows x 48 cols @ st*48] = 1536 cp16 chunks, 6/thread
__device__ __forceinline__ void load_prod(float* sm, uint32_t mb,
                                          const float* Wg, int gs, int st, int tid)
{
    int e = gs >> 1;
    if (e >= 1) mbar_wait(empty_a(mb, gs), (e & 1) ^ 1);
    float* buf = sm + ((gs & 1) ? RG1 : RG0);
    const float* src = Wg + st * 48;
#pragma unroll
    for (int i = 0; i < 6; i++) {
        int q = tid + i * NTH;            // 0..1535
        int n = q / 12, kq = q - n * 12;  // 128 rows x 12 chunks of 4 floats
        cp16(buf + n * LDSP + kq * 4, src + (size_t)n * D_DIM + kq * 4);
    }
    cp_arrive(full_a(mb, gs));
}
// consumer tile: Wc[384 rows x 16 cols @ st*16] = 1536 chunks, 6/thread
__device__ __forceinline__ void load_cons(float* sm, uint32_t mb,
                                          const float* Wbase, int ldw, int gs, int st, int tid)
{
    int e = gs >> 1;
    if (e >= 1) mbar_wait(empty_a(mb, gs), (e & 1) ^ 1);
    float* buf = sm + ((gs & 1) ? RG1 : RG0);
    const float* src = Wbase + st * 16;
#pragma unroll
    for (int i = 0; i < 6; i++) {
        int q = tid + i * NTH;            // 0..1535
        int n = q >> 2, kq = q & 3;       // 384 rows x 4 chunks of 4 floats
        cp16(buf + n * LDSC + kq * 4, src + (size_t)n * ldw + kq * 4);
    }
    cp_arrive(full_a(mb, gs));
}

// ---------------------------------------------------------------------------
// Producer (128-wide): ych[64 x 128] = ACT( xs[64x384] @ Wg[128 x 384]^T + b )
// Warp: pm = w>>2 (2 m16-tiles), pn = w&3 (4 n8-tiles j*32+pn*8).
// 8 k-stages of 48, mbarrier ring. Output RNA-rounded tf32 bits.
// ---------------------------------------------------------------------------
template<int ACT>
__device__ __forceinline__ void producer128(
    const float* __restrict__ Wg, const float* __restrict__ bias,
    float* __restrict__ sm, int pm, int pn, int lane, int tid,
    uint32_t mb, int& g)
{
    float* xs  = sm + XS;
    float* ych = sm + YCH;

    float pacc[32];
#pragma unroll
    for (int i = 0; i < 32; i++) pacc[i] = 0.f;

    load_prod(sm, mb, Wg, g + 0, 0, tid);
    load_prod(sm, mb, Wg, g + 1, 1, tid);
    __syncthreads();   // xs ready (x-form/LN done); prev consumer done with ych

#pragma unroll 1
    for (int st = 0; st < 8; ++st) {
        int gs = g + st;
        mbar_wait(full_a(mb, gs), (gs >> 1) & 1);
        const float* buf = sm + ((gs & 1) ? RG1 : RG0);
#pragma unroll
        for (int k8 = 0; k8 < 6; k8++) {
            uint32_t a[2][4];
#pragma unroll
            for (int mt = 0; mt < 2; mt++) {
                const float* ap = xs + (pm * 32 + mt * 16 + (lane >> 2)) * LDA
                                     + st * 48 + k8 * 8 + (lane & 3);
                a[mt][0] = __float_as_uint(ap[0]);
                a[mt][1] = __float_as_uint(ap[8 * LDA]);
                a[mt][2] = __float_as_uint(ap[4]);
                a[mt][3] = __float_as_uint(ap[8 * LDA + 4]);
            }
#pragma unroll
            for (int j = 0; j < 4; j++) {
                const float* bp = buf + (j * 32 + pn * 8 + (lane >> 2)) * LDSP
                                      + k8 * 8 + (lane & 3);
                uint32_t w0 = __float_as_uint(bp[0]);
                uint32_t w1 = __float_as_uint(bp[4]);
#pragma unroll
                for (int mt = 0; mt < 2; mt++)
                    mma8(pacc + (mt * 4 + j) * 4,
                         a[mt][0], a[mt][1], a[mt][2], a[mt][3], w0, w1);
            }
        }
        if (lane == 0) mbar_arrive(empty_a(mb, gs));
        if (st < 6) load_prod(sm, mb, Wg, g + st + 2, st + 2, tid);
    }
    g += 8;

    // epilogue: bias + activation + RNA tf32 round, write ych
#pragma unroll
    for (int mt = 0; mt < 2; mt++) {
        int r0 = pm * 32 + mt * 16 + (lane >> 2);
#pragma unroll
        for (int j = 0; j < 4; j++) {
            int n0 = j * 32 + pn * 8 + ((lane & 3) << 1);
            float bb0 = bias[n0], bb1 = bias[n0 + 1];
            float v[4];
            v[0] = pacc[(mt * 4 + j) * 4 + 0] + bb0;
            v[1] = pacc[(mt * 4 + j) * 4 + 1] + bb1;
            v[2] = pacc[(mt * 4 + j) * 4 + 2] + bb0;
            v[3] = pacc[(mt * 4 + j) * 4 + 3] + bb1;
#pragma unroll
            for (int cc = 0; cc < 4; cc++) {
                float x = v[cc];
                if (ACT == 1) x = fmaxf(x, 0.f);
                v[cc] = __uint_as_float(f2tf(x));
            }
            ych[r0 * LDY + n0]           = v[0];
            ych[r0 * LDY + n0 + 1]       = v[1];
            ych[(r0 + 8) * LDY + n0]     = v[2];
            ych[(r0 + 8) * LDY + n0 + 1] = v[3];
        }
    }
}

// ---------------------------------------------------------------------------
// Consumer: acc[64 x 384] += ych[64 x 128] @ Wc[384 n x 128 k]^T
// Wbase = Wc + cblk*128. 8 k-stages of 16, mbarrier ring.
// Warp: mg = w>>2 (2 m-tiles), ng = w&3 (12 n-tiles j*32+ng*8).
// ---------------------------------------------------------------------------
__device__ __forceinline__ void consumer128(
    const float* __restrict__ Wc, int ldw, int cblk,
    float* __restrict__ sm, float (&acc)[96],
    int mg, int ng, int lane, int tid, uint32_t mb, int& g)
{
    float* ych = sm + YCH;
    const float* Wbase = Wc + cblk * 128;

    load_cons(sm, mb, Wbase, ldw, g + 0, 0, tid);
    load_cons(sm, mb, Wbase, ldw, g + 1, 1, tid);
    __syncthreads();   // ych fully written by producer epilogues

#pragma unroll 1
    for (int st = 0; st < 8; ++st) {
        int gs = g + st;
        mbar_wait(full_a(mb, gs), (gs >> 1) & 1);
        const float* buf = sm + ((gs & 1) ? RG1 : RG0);
#pragma unroll
        for (int k8 = 0; k8 < 2; k8++) {
            uint32_t a[2][4];
#pragma unroll
            for (int mt = 0; mt < 2; mt++) {
                const float* ap = ych + ((mg * 2 + mt) * 16 + (lane >> 2)) * LDY
                                      + st * 16 + k8 * 8 + (lane & 3);
                a[mt][0] = __float_as_uint(ap[0]);
                a[mt][1] = __float_as_uint(ap[8 * LDY]);
                a[mt][2] = __float_as_uint(ap[4]);
                a[mt][3] = __float_as_uint(ap[8 * LDY + 4]);
            }
#pragma unroll
            for (int j = 0; j < 12; j++) {
                const float* bp = buf + (j * 32 + ng * 8 + (lane >> 2)) * LDSC
                                      + k8 * 8 + (lane & 3);
                uint32_t w0 = __float_as_uint(bp[0]);
                uint32_t w1 = __float_as_uint(bp[4]);
                mma8(acc + (j * 2 + 0) * 4, a[0][0], a[0][1], a[0][2], a[0][3], w0, w1);
                mma8(acc + (j * 2 + 1) * 4, a[1][0], a[1][1], a[1][2], a[1][3], w0, w1);
            }
        }
        if (lane == 0) mbar_arrive(empty_a(mb, gs));
        if (st < 6) load_cons(sm, mb, Wbase, ldw, g + st + 2, st + 2, tid);
    }
    g += 8;
}

// ---------------------------------------------------------------------------
// LN epilogue: xs <- LN(xs + acc) * g + be
// ---------------------------------------------------------------------------
__device__ __forceinline__ void ln_epilogue(
    float* __restrict__ sm, float (&acc)[96],
    const float* __restrict__ g, const float* __restrict__ be,
    int mg, int ng, int lane)
{
    float*  xs  = sm + XS;
    float2* red = reinterpret_cast<float2*>(sm + RED_);

    float s4[4], q4[4];
#pragma unroll
    for (int i = 0; i < 4; i++) { s4[i] = 0.f; q4[i] = 0.f; }

#pragma unroll
    for (int j = 0; j < 12; j++)
#pragma unroll
        for (int mt = 0; mt < 2; mt++)
#pragma unroll
            for (int cc = 0; cc < 4; cc++) {
                int r = mg * 32 + mt * 16 + (lane >> 2) + ((cc >> 1) << 3);
                int n = j * 32 + ng * 8 + ((lane & 3) << 1) + (cc & 1);
                float v = xs[r * LDA + n] + acc[(j * 2 + mt) * 4 + cc];
                xs[r * LDA + n] = v;
                int ri = mt * 2 + (cc >> 1);
                s4[ri] += v;
                q4[ri] += v * v;
            }
#pragma unroll
    for (int d = 1; d < 4; d <<= 1)
#pragma unroll
        for (int i = 0; i < 4; i++) {
            s4[i] += __shfl_xor_sync(0xffffffffu, s4[i], d);
            q4[i] += __shfl_xor_sync(0xffffffffu, q4[i], d);
        }
    if ((lane & 3) == 0) {
#pragma unroll
        for (int i = 0; i < 4; i++) {
            int r = mg * 32 + (i >> 1) * 16 + (lane >> 2) + ((i & 1) << 3);
            red[r * 4 + ng] = make_float2(s4[i], q4[i]);
        }
    }
    __syncthreads();

#pragma unroll
    for (int i = 0; i < 4; i++) {
        int mt = i >> 1, h = i & 1;
        int r = mg * 32 + mt * 16 + (lane >> 2) + h * 8;
        float S = 0.f, Q = 0.f;
#pragma unroll
        for (int w = 0; w < 4; w++) { float2 tv = red[r * 4 + w]; S += tv.x; Q += tv.y; }
        float m   = S * (1.f / 384.f);
        float var = Q * (1.f / 384.f) - m * m;
        float rs  = rsqrtf(var + 1e-5f);
#pragma unroll
        for (int j = 0; j < 12; j++)
#pragma unroll
            for (int cc = 0; cc < 2; cc++) {
                int n = j * 32 + ng * 8 + ((lane & 3) << 1) + cc;
                float v = xs[r * LDA + n];
                xs[r * LDA + n] = (v - m) * rs * g[n] + be[n];
            }
    }
}

// ---------------------------------------------------------------------------
// Decoder producer (64-wide, RNA staging for state-path accuracy):
// ych[64 x 64] = elu( xs @ Wd1[64 x 384]^T + bd1 ), fp32.
// 4 synchronous stages of [64 x 96] into RG0 (bracketed by syncthreads).
// ---------------------------------------------------------------------------
__device__ __forceinline__ void producer_dec(
    const float* __restrict__ Wd1, const float* __restrict__ bias,
    float* __restrict__ sm, int wm, int wn, int lane, int tid)
{
    float* xs  = sm + XS;
    float* ych = sm + YCH;
    float* bt  = sm + RG0;

    float pacc[16];
#pragma unroll
    for (int i = 0; i < 16; i++) pacc[i] = 0.f;

#pragma unroll 1
    for (int st = 0; st < 4; st++) {
        __syncthreads();
#pragma unroll
        for (int i = 0; i < 6; i++) {
            int q = tid + i * NTH;           // 0..1535; 64 rows x 24 chunks
            int n = q / 24, kq = q - n * 24;
            float4 v = *reinterpret_cast<const float4*>(Wd1 + (size_t)n * D_DIM + st * 96 + kq * 4);
            float4 w;
            w.x = __uint_as_float(f2tf(v.x));
            w.y = __uint_as_float(f2tf(v.y));
            w.z = __uint_as_float(f2tf(v.z));
            w.w = __uint_as_float(f2tf(v.w));
            *reinterpret_cast<float4*>(bt + n * LDSD + kq * 4) = w;
        }
        __syncthreads();
#pragma unroll
        for (int k8 = 0; k8 < 12; k8++) {
            const float* ap = xs + (wm * 16 + (lane >> 2)) * LDA + st * 96 + k8 * 8 + (lane & 3);
            uint32_t a0 = f2tf(ap[0]);
            uint32_t a1 = f2tf(ap[8 * LDA]);
            uint32_t a2 = f2tf(ap[4]);
            uint32_t a3 = f2tf(ap[8 * LDA + 4]);
#pragma unroll
            for (int tl = 0; tl < 4; tl++) {
                const float* bp = bt + (wn * 32 + tl * 8 + (lane >> 2)) * LDSD + k8 * 8 + (lane & 3);
                mma8(pacc + tl * 4, a0, a1, a2, a3,
                     __float_as_uint(bp[0]), __float_as_uint(bp[4]));
            }
        }
    }

    int r0 = wm * 16 + (lane >> 2);
#pragma unroll
    for (int tl = 0; tl < 4; tl++) {
        int n0 = wn * 32 + tl * 8 + ((lane & 3) << 1);
        float bb0 = bias[n0], bb1 = bias[n0 + 1];
        float v[4];
        v[0] = pacc[tl * 4 + 0] + bb0;
        v[1] = pacc[tl * 4 + 1] + bb1;
        v[2] = pacc[tl * 4 + 2] + bb0;
        v[3] = pacc[tl * 4 + 3] + bb1;
#pragma unroll
        for (int cc = 0; cc < 4; cc++) { float x = v[cc]; v[cc] = (x > 0.f) ? x : expm1f(x); }
        ych[r0 * LDY + n0]           = v[0];
        ych[r0 * LDY + n0 + 1]       = v[1];
        ych[(r0 + 8) * LDY + n0]     = v[2];
        ych[(r0 + 8) * LDY + n0 + 1] = v[3];
    }
}

__device__ __forceinline__ void cpy(float* __restrict__ dst,
                                    const float* __restrict__ src,
                                    int n, int tid)
{
    for (int i = tid; i < n; i += NTH) dst[i] = src[i];
}

// ---------------------------------------------------------------------------
// Main kernel
// ---------------------------------------------------------------------------
extern "C" __global__ void __launch_bounds__(NTH, 1)
decoder_fused_kernel(
    const float* __restrict__ ih,     const float* __restrict__ plan,
    const float* __restrict__ gate,   const float* __restrict__ init_state,
    const float* __restrict__ Wp,     const float* __restrict__ bp,
    const float* __restrict__ Ws,     const float* __restrict__ bs,
    const float* __restrict__ Wqkv,   const float* __restrict__ bqkv,
    const float* __restrict__ Wo,     const float* __restrict__ bo,
    const float* __restrict__ g1,     const float* __restrict__ be1,
    const float* __restrict__ g2,     const float* __restrict__ be2,
    const float* __restrict__ W1,     const float* __restrict__ b1,
    const float* __restrict__ W2,     const float* __restrict__ b2,
    const float* __restrict__ Wd1,    const float* __restrict__ bd1,
    const float* __restrict__ Wd2,    const float* __restrict__ bd2,
    float* __restrict__ out)
{
    extern __shared__ float sm[];
    const int tid  = threadIdx.x;
    const int lane = tid & 31;
    const int w    = tid >> 5;
    const int pm = w >> 2, pn = w & 3;   // producer128 layout
    const int mg = w >> 2, ng = w & 3;   // consumer layout
    const int wm = w >> 1, wn = w & 1;   // decoder producer layout
    const int row0 = blockIdx.x * 64;

    const float* Wv = Wqkv + 2 * D_DIM * D_DIM;
    const float* bv = bqkv + 2 * D_DIM;

    const uint32_t mb = (uint32_t)__cvta_generic_to_shared(sm + MB_);
    if (tid == 0) {
        mbar_init(mb + 0,  NTH);   // full0  (256 cp-arrives)
        mbar_init(mb + 8,  NTH);   // full1
        mbar_init(mb + 16, 8);     // empty0 (8 warp arrives)
        mbar_init(mb + 24, 8);     // empty1
    }

    // one-time parameter staging
    cpy(sm + WP_,  Wp,  1152, tid);
    cpy(sm + WS_,  Ws,  1152, tid);
    cpy(sm + BP_,  bp,   384, tid);
    cpy(sm + BS_,  bs,   384, tid);
    cpy(sm + BV_,  bv,   384, tid);
    cpy(sm + BO_,  bo,   384, tid);
    cpy(sm + B1_,  b1,  1024, tid);
    cpy(sm + B2_,  b2,   384, tid);
    cpy(sm + G1_,  g1,   384, tid);
    cpy(sm + BE1_, be1,  384, tid);
    cpy(sm + G2_,  g2,   384, tid);
    cpy(sm + BE2_, be2,  384, tid);
    cpy(sm + BD1_, bd1,   64, tid);
    cpy(sm + WD2_, Wd2,  192, tid);
    cpy(sm + BD2_, bd2,    3, tid);
    if (tid < 64)  sm[GATE_  + tid] = gate[row0 + tid];
    if (tid < 192) sm[STATE_ + tid] = init_state[(size_t)row0 * 3 + tid];

    const float* ihrow = ih + (size_t)row0 * D_DIM;
    int g = 0;   // global ring stage counter (uniform across threads)

    for (int t = 0; t < T_STEPS; t++) {
        __syncthreads();   // mbarrier init (t=0) / state+ych from prev step

        if (tid < 192) {
            int r = tid / 3, j = tid - r * 3;
            sm[PLAN_ + tid] = plan[((size_t)(row0 + r) * T_STEPS + t) * 3 + j];
        }
        __syncthreads();

        // x = sf + pf*gate + init_hidden
#pragma unroll 4
        for (int i = 0; i < 96; i++) {
            int idx = tid + i * NTH;
            int r = idx / D_DIM;
            int c = idx - r * D_DIM;
            float p0 = sm[PLAN_ + r * 3], p1 = sm[PLAN_ + r * 3 + 1], p2 = sm[PLAN_ + r * 3 + 2];
            float s0 = sm[STATE_ + r * 3], s1 = sm[STATE_ + r * 3 + 1], s2 = sm[STATE_ + r * 3 + 2];
            float pf = sm[BP_ + c] + p0 * sm[WP_ + c * 3] + p1 * sm[WP_ + c * 3 + 1] + p2 * sm[WP_ + c * 3 + 2];
            float sf = sm[BS_ + c] + s0 * sm[WS_ + c * 3] + s1 * sm[WS_ + c * 3 + 1] + s2 * sm[WS_ + c * 3 + 2];
            sm[XS + r * LDA + c] = sf + pf * sm[GATE_ + r] + ihrow[idx];
        }

        float acc[96];

        // ---- attention: attn = (x @ Wv^T + bv) @ Wo^T + bo
#pragma unroll
        for (int i = 0; i < 96; i++) acc[i] = 0.f;
        for (int c = 0; c < 3; c++) {
            producer128<0>(Wv + (size_t)c * 128 * D_DIM, sm + BV_ + c * 128, sm, pm, pn, lane, tid, mb, g);
            consumer128(Wo, D_DIM, c, sm, acc, mg, ng, lane, tid, mb, g);
        }
#pragma unroll
        for (int j = 0; j < 12; j++)
#pragma unroll
            for (int mt = 0; mt < 2; mt++)
#pragma unroll
                for (int cc = 0; cc < 4; cc++) {
                    int n = j * 32 + ng * 8 + ((lane & 3) << 1) + (cc & 1);
                    acc[(j * 2 + mt) * 4 + cc] += sm[BO_ + n];
                }
        ln_epilogue(sm, acc, sm + G1_, sm + BE1_, mg, ng, lane);

        // ---- FF: h = relu(x @ W1^T + b1) @ W2^T + b2
#pragma unroll
        for (int i = 0; i < 96; i++) acc[i] = 0.f;
        for (int c = 0; c < 8; c++) {
            producer128<1>(W1 + (size_t)c * 128 * D_DIM, sm + B1_ + c * 128, sm, pm, pn, lane, tid, mb, g);
            consumer128(W2, FF_DIM, c, sm, acc, mg, ng, lane, tid, mb, g);
        }
#pragma unroll
        for (int j = 0; j < 12; j++)
#pragma unroll
            for (int mt = 0; mt < 2; mt++)
#pragma unroll
                for (int cc = 0; cc < 4; cc++) {
                    int n = j * 32 + ng * 8 + ((lane & 3) << 1) + (cc & 1);
                    acc[(j * 2 + mt) * 4 + cc] += sm[B2_ + n];
                }
        ln_epilogue(sm, acc, sm + G2_, sm + BE2_, mg, ng, lane);

        // ---- decoder: hid = elu(x @ Wd1^T + bd1)  (fp32, RNA path)
        producer_dec(Wd1, sm + BD1_, sm, wm, wn, lane, tid);
        __syncthreads();

        // upd = hid @ Wd2^T + bd2 ; nxt = state + upd ; emit + carry
        if (tid < 192) {
            int r = tid / 3, i = tid - r * 3;
            float u = sm[BD2_ + i];
            const float* y  = sm + YCH + r * LDY;
            const float* w2 = sm + WD2_ + i * 64;
#pragma unroll 16
            for (int j = 0; j < 64; j++) u += y[j] * w2[j];
            float nxt = sm[STATE_ + r * 3 + i] + u;
            out[((size_t)(row0 + r) * T_STEPS + t) * 3 + i] = nxt;
            sm[STATE_ + r * 3 + i] = nxt;
        }
    }
}

// ---------------------------------------------------------------------------
// launch
// ---------------------------------------------------------------------------
extern "C" void kernel_launch(void* const* d_in, const int* in_sizes, int n_in,
                              void* d_out, int out_size)
{
    (void)in_sizes; (void)n_in; (void)out_size;
    cudaFuncSetAttribute(decoder_fused_kernel,
                         cudaFuncAttributeMaxDynamicSharedMemorySize, SMEM_BYTES);
    decoder_fused_kernel<<<B_TOTAL / 64, NTH, SMEM_BYTES>>>(
        (const float*)d_in[0],  (const float*)d_in[1],  (const float*)d_in[2],
        (const float*)d_in[3],  (const float*)d_in[4],  (const float*)d_in[5],
        (const float*)d_in[6],  (const float*)d_in[7],  (const float*)d_in[8],
        (const float*)d_in[9],  (const float*)d_in[10], (const float*)d_in[11],
        (const float*)d_in[12], (const float*)d_in[13], (const float*)d_in[14],
        (const float*)d_in[15], (const float*)d_in[16], (const float*)d_in[17],
        (const float*)d_in[18], (const float*)d_in[19], (const float*)d_in[20],
        (const float*)d_in[21], (const float*)d_in[22], (const float*)d_in[23],
        (float*)d_out);
}